// round 3
// baseline (speedup 1.0000x reference)
#include <cuda_runtime.h>

#define PH 7
#define PW 7
#define G  7
#define D  8
#define C  (D * G * G)      // 392
#define H  96
#define W  96
#define R  512
#define SCALEF 0.0625f
#define OUT_PER_ROI (D * PH * PW)   // 392
#define MAXEXT 6               // max bin extent: ceil(4.29)+1 = 6

__global__ __launch_bounds__(OUT_PER_ROI, 4) void psroi_kernel(
    const float* __restrict__ feat,   // [B, C, H, W]
    const float* __restrict__ rois,   // [R, 5]
    float* __restrict__ out)          // [R, D, PH, PW]
{
    const int r = blockIdx.x;
    const int t = threadIdx.x;

    __shared__ int   s_b;
    __shared__ int   s_hs[PH], s_he[PH], s_ws[PW], s_we[PW];
    __shared__ float s_invh[PH], s_invw[PW];

    if (t == 0) {
        s_b = (int)rois[r * 5 + 0];
    }
    // vertical bins (p -> rows h), threads 0..6
    if (t < PH) {
        const int p = t;
        float y1 = __fmul_rn(rintf(rois[r * 5 + 2]), SCALEF);
        float y2 = __fmul_rn(rintf(__fadd_rn(rois[r * 5 + 4], 1.0f)), SCALEF);
        float rh = fmaxf(__fsub_rn(y2, y1), 0.1f);
        float bs = __fdiv_rn(rh, (float)PH);
        float s  = fminf(fmaxf(floorf(__fadd_rn(__fmul_rn((float)p,       bs), y1)), 0.0f), (float)H);
        float e  = fminf(fmaxf(ceilf (__fadd_rn(__fmul_rn((float)(p + 1), bs), y1)), 0.0f), (float)H);
        s_hs[p] = (int)s;
        s_he[p] = (int)e;
        float n = fmaxf(__fsub_rn(e, s), 0.0f);
        s_invh[p] = 1.0f / fmaxf(n, 1.0f);
    }
    // horizontal bins (q -> cols w), threads 32..38 (separate warp)
    if (t >= 32 && t < 32 + PW) {
        const int q = t - 32;
        float x1 = __fmul_rn(rintf(rois[r * 5 + 1]), SCALEF);
        float x2 = __fmul_rn(rintf(__fadd_rn(rois[r * 5 + 3], 1.0f)), SCALEF);
        float rw = fmaxf(__fsub_rn(x2, x1), 0.1f);
        float bs = __fdiv_rn(rw, (float)PW);
        float s  = fminf(fmaxf(floorf(__fadd_rn(__fmul_rn((float)q,       bs), x1)), 0.0f), (float)W);
        float e  = fminf(fmaxf(ceilf (__fadd_rn(__fmul_rn((float)(q + 1), bs), x1)), 0.0f), (float)W);
        s_ws[q] = (int)s;
        s_we[q] = (int)e;
        float n = fmaxf(__fsub_rn(e, s), 0.0f);
        s_invw[q] = 1.0f / fmaxf(n, 1.0f);
    }
    __syncthreads();

    // one output element per thread: t = d*49 + p*7 + q == channel c
    const int q = t % PW;
    const int p = (t / PW) % PH;

    const float* fc = feat + ((size_t)s_b * C + t) * (H * W);

    const int hs = s_hs[p], he = s_he[p];
    const int ws = s_ws[q], we = s_we[q];
    const int ew = we - ws;               // 0..6

    const float* base = fc + ws;

    float sum = 0.0f;
    // h unrolled by 2: up to 12 independent predicated loads in flight
    #pragma unroll 1
    for (int h = hs; h < he; h += 2) {
        const float* row0 = base + h * W;
        const bool has1 = (h + 1) < he;
        float v0[MAXEXT], v1[MAXEXT];
        #pragma unroll
        for (int i = 0; i < MAXEXT; ++i) {
            v0[i] = (i < ew)          ? __ldg(row0 + i)     : 0.0f;
        }
        #pragma unroll
        for (int i = 0; i < MAXEXT; ++i) {
            v1[i] = (has1 && i < ew)  ? __ldg(row0 + W + i) : 0.0f;
        }
        float s0 = ((v0[0] + v0[1]) + (v0[2] + v0[3])) + (v0[4] + v0[5]);
        float s1 = ((v1[0] + v1[1]) + (v1[2] + v1[3])) + (v1[4] + v1[5]);
        sum += s0 + s1;
    }
    out[(size_t)r * OUT_PER_ROI + t] = sum * s_invh[p] * s_invw[q];
}

extern "C" void kernel_launch(void* const* d_in, const int* in_sizes, int n_in,
                              void* d_out, int out_size)
{
    const float* feat = (const float*)d_in[0];
    const float* rois = (const float*)d_in[1];
    float* out        = (float*)d_out;
    psroi_kernel<<<R, OUT_PER_ROI>>>(feat, rois, out);
}